// round 14
// baseline (speedup 1.0000x reference)
#include <cuda_runtime.h>
#include <cuda_fp16.h>
#include <cstdint>
#include <math.h>

#define T_TOK 4096
#define H_DIM 2048
#define I_DIM 768
#define E_NUM 8

// ---- scratch (device globals; no allocation allowed) ----
__device__ int    g_cnt[E_NUM];
__device__ int    g_tok[E_NUM * T_TOK];
__device__ float  g_wt [E_NUM * T_TOK];
__device__ __half g_acth[(size_t)E_NUM * T_TOK * I_DIM];
__device__ __half g_xh [(size_t)T_TOK * H_DIM];
__device__ __half g_w0h[(size_t)E_NUM * H_DIM * I_DIM];
__device__ __half g_w1h[(size_t)E_NUM * H_DIM * I_DIM];
__device__ __half g_woh[(size_t)E_NUM * I_DIM * H_DIM];

// ============================ helpers ====================================
__device__ __forceinline__ uint32_t smem_u32(const void* p) {
    uint32_t a;
    asm("{ .reg .u64 t; cvta.to.shared.u64 t, %1; cvt.u32.u64 %0, t; }" : "=r"(a) : "l"(p));
    return a;
}
__device__ __forceinline__ void ldm_x4(uint32_t* r, uint32_t a) {
    asm volatile("ldmatrix.sync.aligned.m8n8.x4.shared.b16 {%0,%1,%2,%3}, [%4];"
                 : "=r"(r[0]), "=r"(r[1]), "=r"(r[2]), "=r"(r[3]) : "r"(a));
}
__device__ __forceinline__ void ldm_x4_t(uint32_t* r, uint32_t a) {
    asm volatile("ldmatrix.sync.aligned.m8n8.x4.trans.shared.b16 {%0,%1,%2,%3}, [%4];"
                 : "=r"(r[0]), "=r"(r[1]), "=r"(r[2]), "=r"(r[3]) : "r"(a));
}
__device__ __forceinline__ void mma16816(float* c, const uint32_t* a, uint32_t b0, uint32_t b1) {
    asm volatile("mma.sync.aligned.m16n8k16.row.col.f32.f16.f16.f32 "
                 "{%0,%1,%2,%3}, {%4,%5,%6,%7}, {%8,%9}, {%0,%1,%2,%3};"
                 : "+f"(c[0]), "+f"(c[1]), "+f"(c[2]), "+f"(c[3])
                 : "r"(a[0]), "r"(a[1]), "r"(a[2]), "r"(a[3]), "r"(b0), "r"(b1));
}
__device__ __forceinline__ void cpa16(uint32_t dst, const void* src, int srcsize) {
    asm volatile("cp.async.cg.shared.global [%0], [%1], 16, %2;"
                 :: "r"(dst), "l"(src), "r"(srcsize) : "memory");
}
#define CP_COMMIT() asm volatile("cp.async.commit_group;" ::: "memory")
#define CP_WAIT1()  asm volatile("cp.async.wait_group 1;" ::: "memory")
#define CP_WAIT0()  asm volatile("cp.async.wait_group 0;" ::: "memory")

// ---------------------------------------------------------------------------
__global__ void k_init() { if (threadIdx.x < E_NUM) g_cnt[threadIdx.x] = 0; }

// fp32 -> fp16 for x, wi0, wi1, wo (one launch)
__global__ void k_cvt4(const float* __restrict__ x,  const float* __restrict__ wi0,
                       const float* __restrict__ wi1, const float* __restrict__ wo) {
    const int NX4 = T_TOK * H_DIM / 4;
    const int NW4 = E_NUM * H_DIM * I_DIM / 4;
    int i = blockIdx.x * blockDim.x + threadIdx.x;
    const float* s; __half* d; int j;
    if (i < NX4)                { s = x;   d = g_xh;  j = i; }
    else if (i < NX4 + NW4)     { s = wi0; d = g_w0h; j = i - NX4; }
    else if (i < NX4 + 2 * NW4) { s = wi1; d = g_w1h; j = i - NX4 - NW4; }
    else if (i < NX4 + 3 * NW4) { s = wo;  d = g_woh; j = i - NX4 - 2 * NW4; }
    else return;
    float4 v = ((const float4*)s)[j];
    __half2 h0 = __floats2half2_rn(v.x, v.y);
    __half2 h1 = __floats2half2_rn(v.z, v.w);
    ((__half2*)d)[2 * j]     = h0;
    ((__half2*)d)[2 * j + 1] = h1;
}

// ---------------------------------------------------------------------------
__global__ void k_router(const float* __restrict__ x, const float* __restrict__ wr,
                         float* __restrict__ out_logits, int write_logits) {
    int warp = threadIdx.x >> 5, lane = threadIdx.x & 31;
    int t = blockIdx.x * 8 + warp;
    if (t >= T_TOK) return;
    float acc[E_NUM];
#pragma unroll
    for (int e = 0; e < E_NUM; e++) acc[e] = 0.f;
    const float* xp = x + (size_t)t * H_DIM;
    for (int h = lane; h < H_DIM; h += 32) {
        float xv = xp[h];
        const float* w = wr + (size_t)h * E_NUM;
#pragma unroll
        for (int e = 0; e < E_NUM; e++) acc[e] += xv * w[e];
    }
#pragma unroll
    for (int e = 0; e < E_NUM; e++)
#pragma unroll
        for (int o = 16; o > 0; o >>= 1)
            acc[e] += __shfl_xor_sync(0xffffffffu, acc[e], o);
    if (lane == 0) {
        if (write_logits)
#pragma unroll
            for (int e = 0; e < E_NUM; e++)
                out_logits[(size_t)t * E_NUM + e] = acc[e];
        int i1 = 0;
#pragma unroll
        for (int e = 1; e < E_NUM; e++) if (acc[e] > acc[i1]) i1 = e;
        int i2 = (i1 == 0) ? 1 : 0;
#pragma unroll
        for (int e = 0; e < E_NUM; e++)
            if (e != i1 && acc[e] > acc[i2]) i2 = e;
        float p2 = expf(acc[i2] - acc[i1]);
        float w1 = 1.f / (1.f + p2), w2 = p2 * w1;
        int p;
        p = atomicAdd(&g_cnt[i1], 1);
        g_tok[i1 * T_TOK + p] = t; g_wt[i1 * T_TOK + p] = w1;
        p = atomicAdd(&g_cnt[i2], 1);
        g_tok[i2 * T_TOK + p] = t; g_wt[i2 * T_TOK + p] = w2;
    }
}

// ---------------------------------------------------------------------------
// GEMM geometry: BM=128, BN=256, BK=32 (two BK=16 sub-stages per barrier),
// 256 thr, warps 2(M)x4(N), warp 64x64. Single-pass fp16. Dynamic smem,
// 3 stages x 24576B; each stage = 2 x (A 4K | B 8K) sub-layouts.
// Pure cp.async fills; 1 sync + 1 wait per BK=32 stage, depth-2 prefetch.
// A rows 32B, swizzle off^(((row>>2)&1)<<4); B rows 512B, ^((k&7)<<4).
#define SUB_B   12288
#define STAGE_B 24576
#define NSTAGE  3

#define COMPUTE_SUB(SB0)                                                      \
    do {                                                                      \
        uint32_t Af[4][4];                                                    \
        _Pragma("unroll")                                                     \
        for (int i = 0; i < 4; i++) {                                         \
            int row = arow_l + i * 16;                                        \
            uint32_t ad = (SB0) + row * 32 +                                  \
                          (acol_l ^ ((((uint32_t)row >> 2) & 1) << 4));       \
            ldm_x4(Af[i], ad);                                                \
        }                                                                     \
        _Pragma("unroll")                                                     \
        for (int jj = 0; jj < 4; jj++) {                                      \
            uint32_t Bf[4];                                                   \
            uint32_t nat = (uint32_t)(bnat_l + jj * 2);                       \
            uint32_t bd = (SB0) + 4096 + bk_l * 512 +                         \
                          ((nat ^ ((uint32_t)bk_l & 7)) << 4);                \
            ldm_x4_t(Bf, bd);                                                 \
            _Pragma("unroll")                                                 \
            for (int i = 0; i < 4; i++) {                                     \
                mma16816(c[i][jj * 2],     Af[i], Bf[0], Bf[1]);              \
                mma16816(c[i][jj * 2 + 1], Af[i], Bf[2], Bf[3]);              \
            }                                                                 \
        }                                                                     \
    } while (0)

// GEMM1: per expert, [Ne,H] x [H, 128 gate + 128 up interleaved by 8] -> act
__global__ __launch_bounds__(256, 1)
void k_mlp1() {
    extern __shared__ __align__(16) char sm[];
    int e  = blockIdx.z;
    int ne = g_cnt[e];
    int m0 = blockIdx.x * 128;
    if (m0 >= ne) return;
    int i0 = blockIdx.y * 128;   // I columns [i0, i0+128)

    int tid = threadIdx.x, lane = tid & 31, wid = tid >> 5;
    int warpM = (wid >> 2) * 64, warpN = (wid & 3) * 64;
    uint32_t sbase = smem_u32(sm);

    // A fill: one 16B unit per thread per sub-stage (gathered rows, fp16 src)
    int ar = tid >> 1;
    uint32_t aswz = (uint32_t)(ar * 32) +
                    (((uint32_t)((tid & 1) * 16)) ^ ((((uint32_t)ar >> 2) & 1) << 4));
    int av16 = ((m0 + ar) < ne) ? 16 : 0;
    const __half* axp = g_xh;
    if (av16) axp = g_xh + (size_t)g_tok[e * T_TOK + m0 + ar] * H_DIM + (tid & 1) * 8;

    // B fill: rows bkk, bkk+8 per sub-stage; nat even -> w0h, odd -> w1h
    int bkk = tid >> 5;
    int nat = tid & 31;
    uint32_t bsw0 = (uint32_t)(bkk * 512) + ((uint32_t)(nat ^ (bkk & 7)) << 4);
    uint32_t bsw1 = bsw0 + 8 * 512;
    size_t wsel = (size_t)e * H_DIM * I_DIM + (size_t)bkk * I_DIM + i0 + (nat >> 1) * 8;
    const __half* bwp = ((nat & 1) ? g_w1h : g_w0h) + wsel;

    float c[4][8][4];
#pragma unroll
    for (int i = 0; i < 4; i++)
#pragma unroll
        for (int j = 0; j < 8; j++)
#pragma unroll
            for (int q = 0; q < 4; q++) c[i][j][q] = 0.f;

    // C = BK32-stage index; k elements [C*32, C*32+32)
#define ISSUE1(S, C) do {                                                     \
    uint32_t s_ = sbase + (S) * STAGE_B;                                      \
    size_t k0_ = (size_t)(C) * 32;                                            \
    cpa16(s_ + aswz,                axp + k0_,                  av16);        \
    cpa16(s_ + 4096 + bsw0,         bwp + k0_ * I_DIM,          16);          \
    cpa16(s_ + 4096 + bsw1,         bwp + (k0_ + 8) * I_DIM,    16);          \
    cpa16(s_ + SUB_B + aswz,        axp + k0_ + 16,             av16);        \
    cpa16(s_ + SUB_B + 4096 + bsw0, bwp + (k0_ + 16) * I_DIM,   16);          \
    cpa16(s_ + SUB_B + 4096 + bsw1, bwp + (k0_ + 24) * I_DIM,   16);          \
    CP_COMMIT();                                                              \
} while (0)

    ISSUE1(0, 0); ISSUE1(1, 1);

    int arow_l = warpM + (lane & 15);
    uint32_t acol_l = (uint32_t)((lane >> 4) * 16);
    int bk_l = (lane & 7) + ((lane >> 3) & 1) * 8;
    int bnat_l = (warpN >> 3) + ((lane >> 4) & 1);

    const int NC = H_DIM / 32;  // 64
    for (int cc = 0; cc < NC; cc++) {
        if (cc + 1 < NC) CP_WAIT1(); else CP_WAIT0();
        __syncthreads();
        if (cc + 2 < NC) ISSUE1((cc + 2) % NSTAGE, cc + 2);
        uint32_t st = sbase + (cc % NSTAGE) * STAGE_B;
        COMPUTE_SUB(st);
        COMPUTE_SUB(st + SUB_B);
    }
#undef ISSUE1

    // Epilogue: accum pairs (2jj, 2jj+1) = (gate, up); silu -> fp16 act.
    int gr = lane >> 2, gc = (lane & 3) * 2;
#pragma unroll
    for (int i = 0; i < 4; i++) {
#pragma unroll
        for (int jj = 0; jj < 4; jj++) {
            int jg = jj * 2, ju = jj * 2 + 1;
            int ic = i0 + ((wid & 3) * 4 + jj) * 8 + gc;
#pragma unroll
            for (int hf = 0; hf < 2; hf++) {
                int slot = m0 + warpM + i * 16 + gr + hf * 8;
                if (slot < ne) {
                    float g0 = c[i][jg][2 * hf], g1 = c[i][jg][2 * hf + 1];
                    float u0 = c[i][ju][2 * hf], u1 = c[i][ju][2 * hf + 1];
                    float a0 = (g0 / (1.f + expf(-g0))) * u0;
                    float a1 = (g1 / (1.f + expf(-g1))) * u1;
                    __half2 hh = __floats2half2_rn(a0, a1);
                    size_t off = ((size_t)e * T_TOK + slot) * I_DIM + ic;
                    *(uint32_t*)(g_acth + off) = *(uint32_t*)&hh;
                }
            }
        }
    }
}

// ---------------------------------------------------------------------------
__global__ __launch_bounds__(256, 1)
void k_mlp2(float* __restrict__ out) {
    extern __shared__ __align__(16) char sm[];
    int e  = blockIdx.z;
    int ne = g_cnt[e];
    int m0 = blockIdx.x * 128;
    if (m0 >= ne) return;
    int n0 = blockIdx.y * 256;

    int tid = threadIdx.x, lane = tid & 31, wid = tid >> 5;
    int warpM = (wid >> 2) * 64, warpN = (wid & 3) * 64;
    uint32_t sbase = smem_u32(sm);

    int ar = tid >> 1;
    uint32_t aswz = (uint32_t)(ar * 32) +
                    (((uint32_t)((tid & 1) * 16)) ^ ((((uint32_t)ar >> 2) & 1) << 4));
    int av16 = ((m0 + ar) < ne) ? 16 : 0;
    const __half* ah = g_acth + ((size_t)e * T_TOK + m0 + ar) * I_DIM + (tid & 1) * 8;

    int bkk = tid >> 5;
    int nat = tid & 31;
    uint32_t bsw0 = (uint32_t)(bkk * 512) + ((uint32_t)(nat ^ (bkk & 7)) << 4);
    uint32_t bsw1 = bsw0 + 8 * 512;
    const __half* bwp = g_woh + (size_t)e * I_DIM * H_DIM + (size_t)bkk * H_DIM + n0 + nat * 8;

    float c[4][8][4];
#pragma unroll
    for (int i = 0; i < 4; i++)
#pragma unroll
        for (int j = 0; j < 8; j++)
#pragma unroll
            for (int q = 0; q < 4; q++) c[i][j][q] = 0.f;

#define ISSUE2(S, C) do {                                                     \
    uint32_t s_ = sbase + (S) * STAGE_B;                                      \
    size_t k0_ = (size_t)(C) * 32;                                            \
    cpa16(s_ + aswz,                ah + k0_,                   av16);        \
    cpa16(s_ + 4096 + bsw0,         bwp + k0_ * H_DIM,          16);          \
    cpa16(s_ + 4096 + bsw1,         bwp + (k0_ + 8) * H_DIM,    16);          \
    cpa16(s_ + SUB_B + aswz,        ah + k0_ + 16,              av16);        \
    cpa16(s_ + SUB_B + 4096 + bsw0, bwp + (k0_ + 16) * H_DIM,   16);          \
    cpa16(s_ + SUB_B + 4096 + bsw1, bwp + (k0_ + 24) * H_DIM,   16);          \
    CP_COMMIT();                                                              \
} while (0)

    ISSUE2(0, 0); ISSUE2(1, 1);

    int arow_l = warpM + (lane & 15);
    uint32_t acol_l = (uint32_t)((lane >> 4) * 16);
    int bk_l = (lane & 7) + ((lane >> 3) & 1) * 8;
    int bnat_l = (warpN >> 3) + ((lane >> 4) & 1);

    const int NC = I_DIM / 32;  // 24
    for (int cc = 0; cc < NC; cc++) {
        if (cc + 1 < NC) CP_WAIT1(); else CP_WAIT0();
        __syncthreads();
        if (cc + 2 < NC) ISSUE2((cc + 2) % NSTAGE, cc + 2);
        uint32_t st = sbase + (cc % NSTAGE) * STAGE_B;
        COMPUTE_SUB(st);
        COMPUTE_SUB(st + SUB_B);
    }
#undef ISSUE2

    int gr = lane >> 2, gc = (lane & 3) * 2;
#pragma unroll
    for (int i = 0; i < 4; i++) {
#pragma unroll
        for (int hf = 0; hf < 2; hf++) {
            int r = m0 + warpM + i * 16 + gr + hf * 8;
            if (r < ne) {
                int   t = g_tok[e * T_TOK + r];
                float w = g_wt [e * T_TOK + r];
                float* op = out + (size_t)t * H_DIM + n0 + warpN;
#pragma unroll
                for (int j = 0; j < 8; j++) {
                    atomicAdd(op + j * 8 + gc,     w * c[i][j][2 * hf]);
                    atomicAdd(op + j * 8 + gc + 1, w * c[i][j][2 * hf + 1]);
                }
            }
        }
    }
}

// ---------------------------------------------------------------------------
extern "C" void kernel_launch(void* const* d_in, const int* in_sizes, int n_in,
                              void* d_out, int out_size) {
    const float* x   = (const float*)d_in[0];
    const float* wr  = (const float*)d_in[1];
    const float* wi0 = (const float*)d_in[2];
    const float* wi1 = (const float*)d_in[3];
    const float* wo  = (const float*)d_in[4];
    float* out = (float*)d_out;

    const int SMEM = NSTAGE * STAGE_B;  // 73728
    cudaFuncSetAttribute(k_mlp1, cudaFuncAttributeMaxDynamicSharedMemorySize, SMEM);
    cudaFuncSetAttribute(k_mlp2, cudaFuncAttributeMaxDynamicSharedMemorySize, SMEM);

    int write_logits = (out_size >= T_TOK * H_DIM + T_TOK * E_NUM) ? 1 : 0;

    cudaMemsetAsync(out, 0, (size_t)T_TOK * H_DIM * sizeof(float));
    k_init<<<1, 32>>>();
    k_router<<<T_TOK / 8, 256>>>(x, wr, out + (size_t)T_TOK * H_DIM, write_logits);

    const int NX4 = T_TOK * H_DIM / 4;
    const int NW4 = E_NUM * H_DIM * I_DIM / 4;
    k_cvt4<<<(NX4 + 3 * NW4 + 255) / 256, 256>>>(x, wi0, wi1, wo);

    dim3 g1(T_TOK / 128, I_DIM / 128, E_NUM);   // (32, 6, 8)
    k_mlp1<<<g1, 256, SMEM>>>();

    dim3 g2(T_TOK / 128, H_DIM / 256, E_NUM);   // (32, 8, 8)
    k_mlp2<<<g2, 256, SMEM>>>(out);
}

// round 15
// speedup vs baseline: 1.1372x; 1.1372x over previous
#include <cuda_runtime.h>
#include <cuda_fp16.h>
#include <cstdint>
#include <math.h>

#define T_TOK 4096
#define H_DIM 2048
#define I_DIM 768
#define E_NUM 8

// ---- scratch (device globals; no allocation allowed) ----
__device__ int    g_cnt[E_NUM];
__device__ int    g_tok[E_NUM * T_TOK];
__device__ float  g_wt [E_NUM * T_TOK];
__device__ __half g_acth[(size_t)E_NUM * T_TOK * I_DIM];
__device__ __half g_xh [(size_t)T_TOK * H_DIM];
// Pre-swizzled B stage tiles (16KB each = 8192 halves), ready for bulk copy.
// mlp1: [e][i0t(6)][kc(64)] ; mlp2: [e][n0t(8)][kc(24)]
__device__ __half g_w01s[(size_t)E_NUM * 6 * 64 * 8192];
__device__ __half g_wos [(size_t)E_NUM * 8 * 24 * 8192];

// ============================ helpers ====================================
__device__ __forceinline__ uint32_t smem_u32(const void* p) {
    uint32_t a;
    asm("{ .reg .u64 t; cvta.to.shared.u64 t, %1; cvt.u32.u64 %0, t; }" : "=r"(a) : "l"(p));
    return a;
}
__device__ __forceinline__ void ldm_x4(uint32_t* r, uint32_t a) {
    asm volatile("ldmatrix.sync.aligned.m8n8.x4.shared.b16 {%0,%1,%2,%3}, [%4];"
                 : "=r"(r[0]), "=r"(r[1]), "=r"(r[2]), "=r"(r[3]) : "r"(a));
}
__device__ __forceinline__ void ldm_x4_t(uint32_t* r, uint32_t a) {
    asm volatile("ldmatrix.sync.aligned.m8n8.x4.trans.shared.b16 {%0,%1,%2,%3}, [%4];"
                 : "=r"(r[0]), "=r"(r[1]), "=r"(r[2]), "=r"(r[3]) : "r"(a));
}
__device__ __forceinline__ void mma16816(float* c, const uint32_t* a, uint32_t b0, uint32_t b1) {
    asm volatile("mma.sync.aligned.m16n8k16.row.col.f32.f16.f16.f32 "
                 "{%0,%1,%2,%3}, {%4,%5,%6,%7}, {%8,%9}, {%0,%1,%2,%3};"
                 : "+f"(c[0]), "+f"(c[1]), "+f"(c[2]), "+f"(c[3])
                 : "r"(a[0]), "r"(a[1]), "r"(a[2]), "r"(a[3]), "r"(b0), "r"(b1));
}
__device__ __forceinline__ void cpa16(uint32_t dst, const void* src, int srcsize) {
    asm volatile("cp.async.cg.shared.global [%0], [%1], 16, %2;"
                 :: "r"(dst), "l"(src), "r"(srcsize) : "memory");
}
#define CP_COMMIT() asm volatile("cp.async.commit_group;" ::: "memory")
#define CP_WAIT1()  asm volatile("cp.async.wait_group 1;" ::: "memory")
#define CP_WAIT0()  asm volatile("cp.async.wait_group 0;" ::: "memory")

__device__ __forceinline__ void bulk16k(uint32_t dst, const void* src, uint32_t mbar) {
    asm volatile("cp.async.bulk.shared::cta.global.mbarrier::complete_tx::bytes "
                 "[%0], [%1], %2, [%3];"
                 :: "r"(dst), "l"(src), "r"(16384u), "r"(mbar) : "memory");
}
#define MBAR_INIT(a, c) \
    asm volatile("mbarrier.init.shared.b64 [%0], %1;" :: "r"(a), "r"((uint32_t)(c)) : "memory")
#define MBAR_EXPECT(a, b) \
    asm volatile("mbarrier.arrive.expect_tx.shared.b64 _, [%0], %1;" :: "r"(a), "r"((uint32_t)(b)) : "memory")
#define MBAR_WAIT(a, p) do {                                                  \
    uint32_t _m = (a), _p = (p), _d;                                          \
    asm volatile("{\n\t.reg .pred q;\n\t"                                     \
        "mbarrier.try_wait.parity.shared.b64 q, [%1], %2;\n\t"                \
        "selp.b32 %0, 1, 0, q;\n\t}" : "=r"(_d) : "r"(_m), "r"(_p) : "memory"); \
    while (!_d) {                                                             \
        asm volatile("{\n\t.reg .pred q;\n\t"                                 \
            "mbarrier.try_wait.parity.shared.b64 q, [%1], %2;\n\t"            \
            "selp.b32 %0, 1, 0, q;\n\t}" : "=r"(_d) : "r"(_m), "r"(_p) : "memory"); \
    }                                                                         \
} while (0)

// convert 8 fp32 -> 8 fp16 (packed uint4)
__device__ __forceinline__ void cvt8(float4 a, float4 b, uint4& H) {
    __half2 h0 = __floats2half2_rn(a.x, a.y);
    __half2 h1 = __floats2half2_rn(a.z, a.w);
    __half2 h2 = __floats2half2_rn(b.x, b.y);
    __half2 h3 = __floats2half2_rn(b.z, b.w);
    H.x = *(uint32_t*)&h0; H.y = *(uint32_t*)&h1;
    H.z = *(uint32_t*)&h2; H.w = *(uint32_t*)&h3;
}

// ---------------------------------------------------------------------------
__global__ void k_init() { if (threadIdx.x < E_NUM) g_cnt[threadIdx.x] = 0; }

// x fp32 -> fp16
__global__ void k_cvtx(const float* __restrict__ x) {
    const int NX4 = T_TOK * H_DIM / 4;
    int i = blockIdx.x * blockDim.x + threadIdx.x;
    if (i >= NX4) return;
    float4 v = ((const float4*)x)[i];
    __half2 h0 = __floats2half2_rn(v.x, v.y);
    __half2 h1 = __floats2half2_rn(v.z, v.w);
    ((__half2*)g_xh)[2 * i]     = h0;
    ((__half2*)g_xh)[2 * i + 1] = h1;
}

// Pre-swizzle mlp1 B tiles: one thread per 16B unit.
__global__ void k_swz1(const float* __restrict__ wi0, const float* __restrict__ wi1) {
    const int TOT = E_NUM * 6 * 65536;  // 3,145,728
    int i = blockIdx.x * blockDim.x + threadIdx.x;
    if (i >= TOT) return;
    int nat = i & 31;
    int kk  = (i >> 5) & 15;
    int sub = (i >> 9) & 1;
    int kc  = (i >> 10) & 63;
    int r   = i >> 16;                 // e*6 + i0t
    int i0t = r % 6, e = r / 6;
    int k  = kc * 32 + sub * 16 + kk;
    int ic = i0t * 128 + (nat >> 1) * 8;
    const float* src = ((nat & 1) ? wi1 : wi0) +
                       ((size_t)e * H_DIM + k) * I_DIM + ic;
    float4 a = *(const float4*)src, b = *(const float4*)(src + 4);
    uint4 H_; cvt8(a, b, H_);
    size_t dst = ((size_t)r * 64 + kc) * 8192 + sub * 4096 + kk * 256 +
                 ((uint32_t)(nat ^ (kk & 7)) << 3);
    *(uint4*)(g_w01s + dst) = H_;
}

// Pre-swizzle mlp2 B tiles.
__global__ void k_swz2(const float* __restrict__ wo) {
    const int TOT = E_NUM * 8 * 24 * 1024;  // 1,572,864
    int i = blockIdx.x * blockDim.x + threadIdx.x;
    if (i >= TOT) return;
    int nat = i & 31;
    int kk  = (i >> 5) & 15;
    int sub = (i >> 9) & 1;
    int t   = i >> 10;
    int kc  = t % 24;
    int r   = t / 24;                  // e*8 + n0t
    int n0t = r % 8, e = r / 8;
    int k = kc * 32 + sub * 16 + kk;
    int h = n0t * 256 + nat * 8;
    const float* src = wo + ((size_t)e * I_DIM + k) * H_DIM + h;
    float4 a = *(const float4*)src, b = *(const float4*)(src + 4);
    uint4 H_; cvt8(a, b, H_);
    size_t dst = ((size_t)r * 24 + kc) * 8192 + sub * 4096 + kk * 256 +
                 ((uint32_t)(nat ^ (kk & 7)) << 3);
    *(uint4*)(g_wos + dst) = H_;
}

// ---------------------------------------------------------------------------
__global__ void k_router(const float* __restrict__ x, const float* __restrict__ wr,
                         float* __restrict__ out_logits, int write_logits) {
    int warp = threadIdx.x >> 5, lane = threadIdx.x & 31;
    int t = blockIdx.x * 8 + warp;
    if (t >= T_TOK) return;
    float acc[E_NUM];
#pragma unroll
    for (int e = 0; e < E_NUM; e++) acc[e] = 0.f;
    const float* xp = x + (size_t)t * H_DIM;
    for (int h = lane; h < H_DIM; h += 32) {
        float xv = xp[h];
        const float* w = wr + (size_t)h * E_NUM;
#pragma unroll
        for (int e = 0; e < E_NUM; e++) acc[e] += xv * w[e];
    }
#pragma unroll
    for (int e = 0; e < E_NUM; e++)
#pragma unroll
        for (int o = 16; o > 0; o >>= 1)
            acc[e] += __shfl_xor_sync(0xffffffffu, acc[e], o);
    if (lane == 0) {
        if (write_logits)
#pragma unroll
            for (int e = 0; e < E_NUM; e++)
                out_logits[(size_t)t * E_NUM + e] = acc[e];
        int i1 = 0;
#pragma unroll
        for (int e = 1; e < E_NUM; e++) if (acc[e] > acc[i1]) i1 = e;
        int i2 = (i1 == 0) ? 1 : 0;
#pragma unroll
        for (int e = 0; e < E_NUM; e++)
            if (e != i1 && acc[e] > acc[i2]) i2 = e;
        float p2 = expf(acc[i2] - acc[i1]);
        float w1 = 1.f / (1.f + p2), w2 = p2 * w1;
        int p;
        p = atomicAdd(&g_cnt[i1], 1);
        g_tok[i1 * T_TOK + p] = t; g_wt[i1 * T_TOK + p] = w1;
        p = atomicAdd(&g_cnt[i2], 1);
        g_tok[i2 * T_TOK + p] = t; g_wt[i2 * T_TOK + p] = w2;
    }
}

// ---------------------------------------------------------------------------
// GEMM geometry: BM=128, BN=256, BK=32, 256 thr, warps 2(M)x4(N), warp 64x64.
// Stage (24576B) = [A0 4K | A1 4K | B 16K(pre-swizzled, filled by 1 bulk)].
// A via cp.async 16B (2/thread/stage); B via cp.async.bulk + mbarrier ring.
// 3 stages. A rows 32B, swizzle off^(((row>>2)&1)<<4); B rows 512B,
// ^((k&7)<<4) on 16B-unit index.
#define STAGE_B 24576
#define NSTAGE  3
#define SMEM_TOTAL (NSTAGE * STAGE_B + 64)

#define COMPUTE_SUB(AB, BB)                                                   \
    do {                                                                      \
        uint32_t Af[4][4];                                                    \
        _Pragma("unroll")                                                     \
        for (int i = 0; i < 4; i++) {                                         \
            int row = arow_l + i * 16;                                        \
            uint32_t ad = (AB) + row * 32 +                                   \
                          (acol_l ^ ((((uint32_t)row >> 2) & 1) << 4));       \
            ldm_x4(Af[i], ad);                                                \
        }                                                                     \
        _Pragma("unroll")                                                     \
        for (int jj = 0; jj < 4; jj++) {                                      \
            uint32_t Bf[4];                                                   \
            uint32_t nat = (uint32_t)(bnat_l + jj * 2);                       \
            uint32_t bd = (BB) + bk_l * 512 +                                 \
                          ((nat ^ ((uint32_t)bk_l & 7)) << 4);                \
            ldm_x4_t(Bf, bd);                                                 \
            _Pragma("unroll")                                                 \
            for (int i = 0; i < 4; i++) {                                     \
                mma16816(c[i][jj * 2],     Af[i], Bf[0], Bf[1]);              \
                mma16816(c[i][jj * 2 + 1], Af[i], Bf[2], Bf[3]);              \
            }                                                                 \
        }                                                                     \
    } while (0)

// GEMM1: per expert, [Ne,H] x [H, 128 gate + 128 up interleaved by 8] -> act
__global__ __launch_bounds__(256, 1)
void k_mlp1() {
    extern __shared__ __align__(16) char sm[];
    int e  = blockIdx.z;
    int ne = g_cnt[e];
    int m0 = blockIdx.x * 128;
    if (m0 >= ne) return;
    int i0t = blockIdx.y;
    int i0 = i0t * 128;

    int tid = threadIdx.x, lane = tid & 31, wid = tid >> 5;
    int warpM = (wid >> 2) * 64, warpN = (wid & 3) * 64;
    uint32_t sbase = smem_u32(sm);
    uint32_t mb = sbase + NSTAGE * STAGE_B;

    if (tid == 0) {
#pragma unroll
        for (int s = 0; s < NSTAGE; s++) MBAR_INIT(mb + s * 8, 1);
    }
    __syncthreads();

    // A fill: one 16B unit per thread per sub (gathered rows, fp16 src)
    int ar = tid >> 1;
    uint32_t aswz = (uint32_t)(ar * 32) +
                    (((uint32_t)((tid & 1) * 16)) ^ ((((uint32_t)ar >> 2) & 1) << 4));
    int av16 = ((m0 + ar) < ne) ? 16 : 0;
    const __half* axp = g_xh;
    if (av16) axp = g_xh + (size_t)g_tok[e * T_TOK + m0 + ar] * H_DIM + (tid & 1) * 8;

    const __half* bsrc = g_w01s + ((size_t)(e * 6 + i0t) * 64) * 8192;

    float c[4][8][4];
#pragma unroll
    for (int i = 0; i < 4; i++)
#pragma unroll
        for (int j = 0; j < 8; j++)
#pragma unroll
            for (int q = 0; q < 4; q++) c[i][j][q] = 0.f;

#define ISSUE1(S, C) do {                                                     \
    uint32_t s_ = sbase + (S) * STAGE_B;                                      \
    cpa16(s_ + aswz,        axp + (size_t)(C) * 32,      av16);               \
    cpa16(s_ + 4096 + aswz, axp + (size_t)(C) * 32 + 16, av16);               \
    CP_COMMIT();                                                              \
    if (tid == 0) {                                                           \
        MBAR_EXPECT(mb + (S) * 8, 16384);                                     \
        bulk16k(s_ + 8192, bsrc + (size_t)(C) * 8192, mb + (S) * 8);          \
    }                                                                         \
} while (0)

    ISSUE1(0, 0); ISSUE1(1, 1);

    int arow_l = warpM + (lane & 15);
    uint32_t acol_l = (uint32_t)((lane >> 4) * 16);
    int bk_l = (lane & 7) + ((lane >> 3) & 1) * 8;
    int bnat_l = (warpN >> 3) + ((lane >> 4) & 1);

    const int NC = H_DIM / 32;  // 64
    for (int cc = 0; cc < NC; cc++) {
        if (cc + 1 < NC) CP_WAIT1(); else CP_WAIT0();
        MBAR_WAIT(mb + (cc % 3) * 8, (cc / 3) & 1);
        __syncthreads();
        if (cc + 2 < NC) ISSUE1((cc + 2) % 3, cc + 2);
        uint32_t st = sbase + (cc % 3) * STAGE_B;
        COMPUTE_SUB(st,        st + 8192);
        COMPUTE_SUB(st + 4096, st + 16384);
    }
#undef ISSUE1

    // Epilogue: accum pairs (2jj, 2jj+1) = (gate, up); silu -> fp16 act.
    int gr = lane >> 2, gc = (lane & 3) * 2;
#pragma unroll
    for (int i = 0; i < 4; i++) {
#pragma unroll
        for (int jj = 0; jj < 4; jj++) {
            int jg = jj * 2, ju = jj * 2 + 1;
            int ic = i0 + ((wid & 3) * 4 + jj) * 8 + gc;
#pragma unroll
            for (int hf = 0; hf < 2; hf++) {
                int slot = m0 + warpM + i * 16 + gr + hf * 8;
                if (slot < ne) {
                    float g0 = c[i][jg][2 * hf], g1 = c[i][jg][2 * hf + 1];
                    float u0 = c[i][ju][2 * hf], u1 = c[i][ju][2 * hf + 1];
                    float a0 = (g0 / (1.f + expf(-g0))) * u0;
                    float a1 = (g1 / (1.f + expf(-g1))) * u1;
                    __half2 hh = __floats2half2_rn(a0, a1);
                    size_t off = ((size_t)e * T_TOK + slot) * I_DIM + ic;
                    *(uint32_t*)(g_acth + off) = *(uint32_t*)&hh;
                }
            }
        }
    }
}

// ---------------------------------------------------------------------------
__global__ __launch_bounds__(256, 1)
void k_mlp2(float* __restrict__ out) {
    extern __shared__ __align__(16) char sm[];
    int e  = blockIdx.z;
    int ne = g_cnt[e];
    int m0 = blockIdx.x * 128;
    if (m0 >= ne) return;
    int n0t = blockIdx.y;
    int n0 = n0t * 256;

    int tid = threadIdx.x, lane = tid & 31, wid = tid >> 5;
    int warpM = (wid >> 2) * 64, warpN = (wid & 3) * 64;
    uint32_t sbase = smem_u32(sm);
    uint32_t mb = sbase + NSTAGE * STAGE_B;

    if (tid == 0) {
#pragma unroll
        for (int s = 0; s < NSTAGE; s++) MBAR_INIT(mb + s * 8, 1);
    }
    __syncthreads();

    int ar = tid >> 1;
    uint32_t aswz = (uint32_t)(ar * 32) +
                    (((uint32_t)((tid & 1) * 16)) ^ ((((uint32_t)ar >> 2) & 1) << 4));
    int av16 = ((m0 + ar) < ne) ? 16 : 0;
    const __half* ah = g_acth + ((size_t)e * T_TOK + m0 + ar) * I_DIM + (tid & 1) * 8;

    const __half* bsrc = g_wos + ((size_t)(e * 8 + n0t) * 24) * 8192;

    float c[4][8][4];
#pragma unroll
    for (int i = 0; i < 4; i++)
#pragma unroll
        for (int j = 0; j < 8; j++)
#pragma unroll
            for (int q = 0; q < 4; q++) c[i][j][q] = 0.f;

#define ISSUE2(S, C) do {                                                     \
    uint32_t s_ = sbase + (S) * STAGE_B;                                      \
    cpa16(s_ + aswz,        ah + (size_t)(C) * 32,      av16);                \
    cpa16(s_ + 4096 + aswz, ah + (size_t)(C) * 32 + 16, av16);                \
    CP_COMMIT();                                                              \
    if (tid == 0) {                                                           \
        MBAR_EXPECT(mb + (S) * 8, 16384);                                     \
        bulk16k(s_ + 8192, bsrc + (size_t)(C) * 8192, mb + (S) * 8);          \
    }                                                                         \
} while (0)

    ISSUE2(0, 0); ISSUE2(1, 1);

    int arow_l = warpM + (lane & 15);
    uint32_t acol_l = (uint32_t)((lane >> 4) * 16);
    int bk_l = (lane & 7) + ((lane >> 3) & 1) * 8;
    int bnat_l = (warpN >> 3) + ((lane >> 4) & 1);

    const int NC = I_DIM / 32;  // 24
    for (int cc = 0; cc < NC; cc++) {
        if (cc + 1 < NC) CP_WAIT1(); else CP_WAIT0();
        MBAR_WAIT(mb + (cc % 3) * 8, (cc / 3) & 1);
        __syncthreads();
        if (cc + 2 < NC) ISSUE2((cc + 2) % 3, cc + 2);
        uint32_t st = sbase + (cc % 3) * STAGE_B;
        COMPUTE_SUB(st,        st + 8192);
        COMPUTE_SUB(st + 4096, st + 16384);
    }
#undef ISSUE2

    int gr = lane >> 2, gc = (lane & 3) * 2;
#pragma unroll
    for (int i = 0; i < 4; i++) {
#pragma unroll
        for (int hf = 0; hf < 2; hf++) {
            int r = m0 + warpM + i * 16 + gr + hf * 8;
            if (r < ne) {
                int   t = g_tok[e * T_TOK + r];
                float w = g_wt [e * T_TOK + r];
                float* op = out + (size_t)t * H_DIM + n0 + warpN;
#pragma unroll
                for (int j = 0; j < 8; j++) {
                    atomicAdd(op + j * 8 + gc,     w * c[i][j][2 * hf]);
                    atomicAdd(op + j * 8 + gc + 1, w * c[i][j][2 * hf + 1]);
                }
            }
        }
    }
}

// ---------------------------------------------------------------------------
extern "C" void kernel_launch(void* const* d_in, const int* in_sizes, int n_in,
                              void* d_out, int out_size) {
    const float* x   = (const float*)d_in[0];
    const float* wr  = (const float*)d_in[1];
    const float* wi0 = (const float*)d_in[2];
    const float* wi1 = (const float*)d_in[3];
    const float* wo  = (const float*)d_in[4];
    float* out = (float*)d_out;

    cudaFuncSetAttribute(k_mlp1, cudaFuncAttributeMaxDynamicSharedMemorySize, SMEM_TOTAL);
    cudaFuncSetAttribute(k_mlp2, cudaFuncAttributeMaxDynamicSharedMemorySize, SMEM_TOTAL);

    int write_logits = (out_size >= T_TOK * H_DIM + T_TOK * E_NUM) ? 1 : 0;

    cudaMemsetAsync(out, 0, (size_t)T_TOK * H_DIM * sizeof(float));
    k_init<<<1, 32>>>();
    k_router<<<T_TOK / 8, 256>>>(x, wr, out + (size_t)T_TOK * H_DIM, write_logits);

    const int NX4 = T_TOK * H_DIM / 4;
    k_cvtx<<<(NX4 + 255) / 256, 256>>>(x);
    k_swz1<<<(E_NUM * 6 * 65536 + 255) / 256, 256>>>(wi0, wi1);
    k_swz2<<<(E_NUM * 8 * 24 * 1024 + 255) / 256, 256>>>(wo);

    dim3 g1(T_TOK / 128, 6, E_NUM);
    k_mlp1<<<g1, 256, SMEM_TOTAL>>>();

    dim3 g2(T_TOK / 128, 8, E_NUM);
    k_mlp2<<<g2, 256, SMEM_TOTAL>>>(out);
}

// round 16
// speedup vs baseline: 1.2286x; 1.0804x over previous
#include <cuda_runtime.h>
#include <cuda_fp16.h>
#include <cstdint>
#include <math.h>

#define T_TOK 4096
#define H_DIM 2048
#define I_DIM 768
#define E_NUM 8

// ---- scratch (device globals; no allocation allowed) ----
__device__ int    g_cnt[E_NUM];
__device__ int    g_tok[E_NUM * T_TOK];
__device__ float  g_wt [E_NUM * T_TOK];
// Pre-swizzled A stage tiles (8KB = 4096 halves each):
//   g_xs  : [e][m0t(32)][kc(64)]  (gathered x rows, k over H)
//   g_acts: [e][m0t(32)][kc(24)]  (activations, k over I; written by mlp1)
__device__ __half g_xs  [(size_t)E_NUM * 32 * 64 * 4096];
__device__ __half g_acts[(size_t)E_NUM * 32 * 24 * 4096];
// Pre-swizzled B stage tiles (16KB = 8192 halves each):
//   g_w01s: [e][i0t(6)][kc(64)] ; g_wos: [e][n0t(8)][kc(24)]
__device__ __half g_w01s[(size_t)E_NUM * 6 * 64 * 8192];
__device__ __half g_wos [(size_t)E_NUM * 8 * 24 * 8192];

// ============================ helpers ====================================
__device__ __forceinline__ uint32_t smem_u32(const void* p) {
    uint32_t a;
    asm("{ .reg .u64 t; cvta.to.shared.u64 t, %1; cvt.u32.u64 %0, t; }" : "=r"(a) : "l"(p));
    return a;
}
__device__ __forceinline__ void ldm_x4(uint32_t* r, uint32_t a) {
    asm volatile("ldmatrix.sync.aligned.m8n8.x4.shared.b16 {%0,%1,%2,%3}, [%4];"
                 : "=r"(r[0]), "=r"(r[1]), "=r"(r[2]), "=r"(r[3]) : "r"(a));
}
__device__ __forceinline__ void ldm_x4_t(uint32_t* r, uint32_t a) {
    asm volatile("ldmatrix.sync.aligned.m8n8.x4.trans.shared.b16 {%0,%1,%2,%3}, [%4];"
                 : "=r"(r[0]), "=r"(r[1]), "=r"(r[2]), "=r"(r[3]) : "r"(a));
}
__device__ __forceinline__ void mma16816(float* c, const uint32_t* a, uint32_t b0, uint32_t b1) {
    asm volatile("mma.sync.aligned.m16n8k16.row.col.f32.f16.f16.f32 "
                 "{%0,%1,%2,%3}, {%4,%5,%6,%7}, {%8,%9}, {%0,%1,%2,%3};"
                 : "+f"(c[0]), "+f"(c[1]), "+f"(c[2]), "+f"(c[3])
                 : "r"(a[0]), "r"(a[1]), "r"(a[2]), "r"(a[3]), "r"(b0), "r"(b1));
}
__device__ __forceinline__ void bulkN(uint32_t dst, const void* src, uint32_t bytes,
                                      uint32_t mbar) {
    asm volatile("cp.async.bulk.shared::cta.global.mbarrier::complete_tx::bytes "
                 "[%0], [%1], %2, [%3];"
                 :: "r"(dst), "l"(src), "r"(bytes), "r"(mbar) : "memory");
}
#define FENCE_PROXY_ASYNC() asm volatile("fence.proxy.async.shared::cta;" ::: "memory")
#define MBAR_INIT(a, c) \
    asm volatile("mbarrier.init.shared.b64 [%0], %1;" :: "r"(a), "r"((uint32_t)(c)) : "memory")
#define MBAR_EXPECT(a, b) \
    asm volatile("mbarrier.arrive.expect_tx.shared.b64 _, [%0], %1;" :: "r"(a), "r"((uint32_t)(b)) : "memory")
#define MBAR_WAIT(a, p) do {                                                  \
    uint32_t _m = (a), _p = (p), _d;                                          \
    asm volatile("{\n\t.reg .pred q;\n\t"                                     \
        "mbarrier.try_wait.parity.shared.b64 q, [%1], %2;\n\t"                \
        "selp.b32 %0, 1, 0, q;\n\t}" : "=r"(_d) : "r"(_m), "r"(_p) : "memory"); \
    while (!_d) {                                                             \
        asm volatile("{\n\t.reg .pred q;\n\t"                                 \
            "mbarrier.try_wait.parity.shared.b64 q, [%1], %2;\n\t"            \
            "selp.b32 %0, 1, 0, q;\n\t}" : "=r"(_d) : "r"(_m), "r"(_p) : "memory"); \
    }                                                                         \
} while (0)

// convert 8 fp32 -> 8 fp16 (packed uint4)
__device__ __forceinline__ void cvt8(float4 a, float4 b, uint4& H) {
    __half2 h0 = __floats2half2_rn(a.x, a.y);
    __half2 h1 = __floats2half2_rn(a.z, a.w);
    __half2 h2 = __floats2half2_rn(b.x, b.y);
    __half2 h3 = __floats2half2_rn(b.z, b.w);
    H.x = *(uint32_t*)&h0; H.y = *(uint32_t*)&h1;
    H.z = *(uint32_t*)&h2; H.w = *(uint32_t*)&h3;
}

// ---------------------------------------------------------------------------
__global__ void k_init() { if (threadIdx.x < E_NUM) g_cnt[threadIdx.x] = 0; }

// ---------------------------------------------------------------------------
__global__ void k_router(const float* __restrict__ x, const float* __restrict__ wr,
                         float* __restrict__ out_logits, int write_logits) {
    int warp = threadIdx.x >> 5, lane = threadIdx.x & 31;
    int t = blockIdx.x * 8 + warp;
    if (t >= T_TOK) return;
    float acc[E_NUM];
#pragma unroll
    for (int e = 0; e < E_NUM; e++) acc[e] = 0.f;
    const float* xp = x + (size_t)t * H_DIM;
    for (int h = lane; h < H_DIM; h += 32) {
        float xv = xp[h];
        const float* w = wr + (size_t)h * E_NUM;
#pragma unroll
        for (int e = 0; e < E_NUM; e++) acc[e] += xv * w[e];
    }
#pragma unroll
    for (int e = 0; e < E_NUM; e++)
#pragma unroll
        for (int o = 16; o > 0; o >>= 1)
            acc[e] += __shfl_xor_sync(0xffffffffu, acc[e], o);
    if (lane == 0) {
        if (write_logits)
#pragma unroll
            for (int e = 0; e < E_NUM; e++)
                out_logits[(size_t)t * E_NUM + e] = acc[e];
        int i1 = 0;
#pragma unroll
        for (int e = 1; e < E_NUM; e++) if (acc[e] > acc[i1]) i1 = e;
        int i2 = (i1 == 0) ? 1 : 0;
#pragma unroll
        for (int e = 0; e < E_NUM; e++)
            if (e != i1 && acc[e] > acc[i2]) i2 = e;
        float p2 = expf(acc[i2] - acc[i1]);
        float w1 = 1.f / (1.f + p2), w2 = p2 * w1;
        int p;
        p = atomicAdd(&g_cnt[i1], 1);
        g_tok[i1 * T_TOK + p] = t; g_wt[i1 * T_TOK + p] = w1;
        p = atomicAdd(&g_cnt[i2], 1);
        g_tok[i2 * T_TOK + p] = t; g_wt[i2 * T_TOK + p] = w2;
    }
}

// ---------------------------------------------------------------------------
// Pre-swizzle mlp1 B tiles: one thread per 16B unit.
__global__ void k_swz1(const float* __restrict__ wi0, const float* __restrict__ wi1) {
    const int TOT = E_NUM * 6 * 65536;
    int i = blockIdx.x * blockDim.x + threadIdx.x;
    if (i >= TOT) return;
    int nat = i & 31;
    int kk  = (i >> 5) & 15;
    int sub = (i >> 9) & 1;
    int kc  = (i >> 10) & 63;
    int r   = i >> 16;                 // e*6 + i0t
    int i0t = r % 6, e = r / 6;
    int k  = kc * 32 + sub * 16 + kk;
    int ic = i0t * 128 + (nat >> 1) * 8;
    const float* src = ((nat & 1) ? wi1 : wi0) +
                       ((size_t)e * H_DIM + k) * I_DIM + ic;
    float4 a = *(const float4*)src, b = *(const float4*)(src + 4);
    uint4 H_; cvt8(a, b, H_);
    size_t dst = ((size_t)r * 64 + kc) * 8192 + sub * 4096 + kk * 256 +
                 ((uint32_t)(nat ^ (kk & 7)) << 3);
    *(uint4*)(g_w01s + dst) = H_;
}

// Pre-swizzle mlp2 B tiles.
__global__ void k_swz2(const float* __restrict__ wo) {
    const int TOT = E_NUM * 8 * 24 * 1024;
    int i = blockIdx.x * blockDim.x + threadIdx.x;
    if (i >= TOT) return;
    int nat = i & 31;
    int kk  = (i >> 5) & 15;
    int sub = (i >> 9) & 1;
    int t   = i >> 10;
    int kc  = t % 24;
    int r   = t / 24;                  // e*8 + n0t
    int n0t = r % 8, e = r / 8;
    int k = kc * 32 + sub * 16 + kk;
    int h = n0t * 256 + nat * 8;
    const float* src = wo + ((size_t)e * I_DIM + k) * H_DIM + h;
    float4 a = *(const float4*)src, b = *(const float4*)(src + 4);
    uint4 H_; cvt8(a, b, H_);
    size_t dst = ((size_t)r * 24 + kc) * 8192 + sub * 4096 + kk * 256 +
                 ((uint32_t)(nat ^ (kk & 7)) << 3);
    *(uint4*)(g_wos + dst) = H_;
}

// Gather routed token rows into pre-swizzled A tiles (after router).
// One thread per 16B unit: [e][m0t][kc][sub(2)][row(128)][u(2)]
__global__ void k_gath(const float* __restrict__ x) {
    int i = blockIdx.x * blockDim.x + threadIdx.x;
    if (i >= E_NUM * 32 * 64 * 512) return;
    int u    = i & 1;
    int row  = (i >> 1) & 127;
    int sub  = (i >> 8) & 1;
    int kc   = (i >> 9) & 63;
    int m0t  = (i >> 15) & 31;
    int e    = i >> 20;
    int ne = g_cnt[e];
    if (m0t * 128 >= ne) return;
    int slot = m0t * 128 + row;
    uint4 H_ = make_uint4(0, 0, 0, 0);
    if (slot < ne) {
        int tok = g_tok[e * T_TOK + slot];
        int k = kc * 32 + sub * 16 + u * 8;
        const float* s = x + (size_t)tok * H_DIM + k;
        cvt8(*(const float4*)s, *(const float4*)(s + 4), H_);
    }
    size_t dst = (((size_t)(e * 32 + m0t) * 64 + kc) * 4096) + sub * 2048 +
                 row * 16 + (uint32_t)((u * 8) ^ (((row >> 2) & 1) << 3));
    *(uint4*)(g_xs + dst) = H_;
}

// ---------------------------------------------------------------------------
// GEMM geometry: BM=128, BN=256, BK=32, 256 thr, warps 2(M)x4(N), warp 64x64.
// Stage (24576B) = [A 8K | B 16K], BOTH filled by cp.async.bulk from
// pre-swizzled gmem tiles; one mbarrier per stage (expect 24576B). 3 stages.
// A rows 32B, swizzle off^(((row>>2)&1)<<4); B rows 512B, ^((k&7)<<4).
#define STAGE_B 24576
#define NSTAGE  3
#define SMEM_TOTAL (NSTAGE * STAGE_B + 64)

#define COMPUTE_SUB(AB, BB)                                                   \
    do {                                                                      \
        uint32_t Af[4][4];                                                    \
        _Pragma("unroll")                                                     \
        for (int i = 0; i < 4; i++) {                                         \
            int row = arow_l + i * 16;                                        \
            uint32_t ad = (AB) + row * 32 +                                   \
                          (acol_l ^ ((((uint32_t)row >> 2) & 1) << 4));       \
            ldm_x4(Af[i], ad);                                                \
        }                                                                     \
        _Pragma("unroll")                                                     \
        for (int jj = 0; jj < 4; jj++) {                                      \
            uint32_t Bf[4];                                                   \
            uint32_t nat = (uint32_t)(bnat_l + jj * 2);                       \
            uint32_t bd = (BB) + bk_l * 512 +                                 \
                          ((nat ^ ((uint32_t)bk_l & 7)) << 4);                \
            ldm_x4_t(Bf, bd);                                                 \
            _Pragma("unroll")                                                 \
            for (int i = 0; i < 4; i++) {                                     \
                mma16816(c[i][jj * 2],     Af[i], Bf[0], Bf[1]);              \
                mma16816(c[i][jj * 2 + 1], Af[i], Bf[2], Bf[3]);              \
            }                                                                 \
        }                                                                     \
    } while (0)

#define ISSUE_BULK(S, C) do {                                                 \
    if (tid == 0) {                                                           \
        uint32_t s_ = sbase + (S) * STAGE_B;                                  \
        FENCE_PROXY_ASYNC();                                                  \
        MBAR_EXPECT(mb + (S) * 8, 24576);                                     \
        bulkN(s_,        asrc + (size_t)(C) * 4096, 8192,  mb + (S) * 8);     \
        bulkN(s_ + 8192, bsrc + (size_t)(C) * 8192, 16384, mb + (S) * 8);     \
    }                                                                         \
} while (0)

// GEMM1: per expert, [Ne,H] x [H, 128 gate + 128 up interleaved by 8] -> act
__global__ __launch_bounds__(256, 1)
void k_mlp1() {
    extern __shared__ __align__(16) char sm[];
    int e   = blockIdx.z;
    int ne  = g_cnt[e];
    int m0t = blockIdx.x;
    int m0  = m0t * 128;
    if (m0 >= ne) return;
    int i0t = blockIdx.y;
    int i0  = i0t * 128;

    int tid = threadIdx.x, lane = tid & 31, wid = tid >> 5;
    int warpM = (wid >> 2) * 64, warpN = (wid & 3) * 64;
    uint32_t sbase = smem_u32(sm);
    uint32_t mb = sbase + NSTAGE * STAGE_B;

    if (tid == 0) {
#pragma unroll
        for (int s = 0; s < NSTAGE; s++) MBAR_INIT(mb + s * 8, 1);
    }
    __syncthreads();

    const __half* asrc = g_xs   + ((size_t)(e * 32 + m0t) * 64) * 4096;
    const __half* bsrc = g_w01s + ((size_t)(e * 6 + i0t) * 64) * 8192;

    float c[4][8][4];
#pragma unroll
    for (int i = 0; i < 4; i++)
#pragma unroll
        for (int j = 0; j < 8; j++)
#pragma unroll
            for (int q = 0; q < 4; q++) c[i][j][q] = 0.f;

    ISSUE_BULK(0, 0); ISSUE_BULK(1, 1);

    int arow_l = warpM + (lane & 15);
    uint32_t acol_l = (uint32_t)((lane >> 4) * 16);
    int bk_l = (lane & 7) + ((lane >> 3) & 1) * 8;
    int bnat_l = (warpN >> 3) + ((lane >> 4) & 1);

    const int NC = H_DIM / 32;  // 64
    for (int cc = 0; cc < NC; cc++) {
        MBAR_WAIT(mb + (cc % 3) * 8, (cc / 3) & 1);
        __syncthreads();
        if (cc + 2 < NC) ISSUE_BULK((cc + 2) % 3, cc + 2);
        uint32_t st = sbase + (cc % 3) * STAGE_B;
        COMPUTE_SUB(st,        st + 8192);
        COMPUTE_SUB(st + 4096, st + 16384);
    }

    // Epilogue: pairs (2jj, 2jj+1) = (gate, up); silu -> pre-swizzled act tile
    int gr = lane >> 2, gc = (lane & 3) * 2;
#pragma unroll
    for (int i = 0; i < 4; i++) {
#pragma unroll
        for (int jj = 0; jj < 4; jj++) {
            int jg = jj * 2, ju = jj * 2 + 1;
            int icg = i0 + ((wid & 3) * 4 + jj) * 8 + gc;  // global I col
#pragma unroll
            for (int hf = 0; hf < 2; hf++) {
                int r = warpM + i * 16 + gr + hf * 8;      // local row
                if (m0 + r < ne) {
                    float g0 = c[i][jg][2 * hf], g1 = c[i][jg][2 * hf + 1];
                    float u0 = c[i][ju][2 * hf], u1 = c[i][ju][2 * hf + 1];
                    float a0 = (g0 / (1.f + expf(-g0))) * u0;
                    float a1 = (g1 / (1.f + expf(-g1))) * u1;
                    __half2 hh = __floats2half2_rn(a0, a1);
                    int kc2 = icg >> 5, sub2 = (icg >> 4) & 1;
                    int u2 = (icg >> 3) & 1, b2 = icg & 7;
                    size_t off = (((size_t)(e * 32 + m0t) * 24 + kc2) * 4096) +
                                 sub2 * 2048 + r * 16 +
                                 (uint32_t)((u2 * 8) ^ (((r >> 2) & 1) << 3)) + b2;
                    *(uint32_t*)(g_acts + off) = *(uint32_t*)&hh;
                }
            }
        }
    }
}

// ---------------------------------------------------------------------------
__global__ __launch_bounds__(256, 1)
void k_mlp2(float* __restrict__ out) {
    extern __shared__ __align__(16) char sm[];
    int e   = blockIdx.z;
    int ne  = g_cnt[e];
    int m0t = blockIdx.x;
    int m0  = m0t * 128;
    if (m0 >= ne) return;
    int n0t = blockIdx.y;
    int n0  = n0t * 256;

    int tid = threadIdx.x, lane = tid & 31, wid = tid >> 5;
    int warpM = (wid >> 2) * 64, warpN = (wid & 3) * 64;
    uint32_t sbase = smem_u32(sm);
    uint32_t mb = sbase + NSTAGE * STAGE_B;

    if (tid == 0) {
#pragma unroll
        for (int s = 0; s < NSTAGE; s++) MBAR_INIT(mb + s * 8, 1);
    }
    __syncthreads();

    const __half* asrc = g_acts + ((size_t)(e * 32 + m0t) * 24) * 4096;
    const __half* bsrc = g_wos  + ((size_t)(e * 8 + n0t) * 24) * 8192;

    float c[4][8][4];
#pragma unroll
    for (int i = 0; i < 4; i++)
#pragma unroll
        for (int j = 0; j < 8; j++)
#pragma unroll
            for (int q = 0; q < 4; q++) c[i][j][q] = 0.f;

    ISSUE_BULK(0, 0); ISSUE_BULK(1, 1);

    int arow_l = warpM + (lane & 15);
    uint32_t acol_l = (uint32_t)((lane >> 4) * 16);
    int bk_l = (lane & 7) + ((lane >> 3) & 1) * 8;
    int bnat_l = (warpN >> 3) + ((lane >> 4) & 1);

    const int NC = I_DIM / 32;  // 24
    for (int cc = 0; cc < NC; cc++) {
        MBAR_WAIT(mb + (cc % 3) * 8, (cc / 3) & 1);
        __syncthreads();
        if (cc + 2 < NC) ISSUE_BULK((cc + 2) % 3, cc + 2);
        uint32_t st = sbase + (cc % 3) * STAGE_B;
        COMPUTE_SUB(st,        st + 8192);
        COMPUTE_SUB(st + 4096, st + 16384);
    }

    int gr = lane >> 2, gc = (lane & 3) * 2;
#pragma unroll
    for (int i = 0; i < 4; i++) {
#pragma unroll
        for (int hf = 0; hf < 2; hf++) {
            int r = m0 + warpM + i * 16 + gr + hf * 8;
            if (r < ne) {
                int   t = g_tok[e * T_TOK + r];
                float w = g_wt [e * T_TOK + r];
                float* op = out + (size_t)t * H_DIM + n0 + warpN;
#pragma unroll
                for (int j = 0; j < 8; j++) {
                    atomicAdd(op + j * 8 + gc,     w * c[i][j][2 * hf]);
                    atomicAdd(op + j * 8 + gc + 1, w * c[i][j][2 * hf + 1]);
                }
            }
        }
    }
}

// ---------------------------------------------------------------------------
extern "C" void kernel_launch(void* const* d_in, const int* in_sizes, int n_in,
                              void* d_out, int out_size) {
    const float* x   = (const float*)d_in[0];
    const float* wr  = (const float*)d_in[1];
    const float* wi0 = (const float*)d_in[2];
    const float* wi1 = (const float*)d_in[3];
    const float* wo  = (const float*)d_in[4];
    float* out = (float*)d_out;

    cudaFuncSetAttribute(k_mlp1, cudaFuncAttributeMaxDynamicSharedMemorySize, SMEM_TOTAL);
    cudaFuncSetAttribute(k_mlp2, cudaFuncAttributeMaxDynamicSharedMemorySize, SMEM_TOTAL);

    int write_logits = (out_size >= T_TOK * H_DIM + T_TOK * E_NUM) ? 1 : 0;

    cudaMemsetAsync(out, 0, (size_t)T_TOK * H_DIM * sizeof(float));
    k_init<<<1, 32>>>();
    k_router<<<T_TOK / 8, 256>>>(x, wr, out + (size_t)T_TOK * H_DIM, write_logits);

    k_swz1<<<(E_NUM * 6 * 65536 + 255) / 256, 256>>>(wi0, wi1);
    k_swz2<<<(E_NUM * 8 * 24 * 1024 + 255) / 256, 256>>>(wo);
    k_gath<<<(E_NUM * 32 * 64 * 512 + 255) / 256, 256>>>(x);

    dim3 g1(32, 6, E_NUM);
    k_mlp1<<<g1, 256, SMEM_TOTAL>>>();

    dim3 g2(32, 8, E_NUM);
    k_mlp2<<<g2, 256, SMEM_TOTAL>>>(out);
}

// round 17
// speedup vs baseline: 1.2363x; 1.0063x over previous
#include <cuda_runtime.h>
#include <cuda_fp16.h>
#include <cstdint>
#include <math.h>

#define T_TOK 4096
#define H_DIM 2048
#define I_DIM 768
#define E_NUM 8

// ---- scratch (device globals; no allocation allowed) ----
__device__ int    g_cnt[E_NUM];
__device__ int    g_tok[E_NUM * T_TOK];
__device__ float  g_wt [E_NUM * T_TOK];
__device__ int    g_dst[E_NUM * T_TOK];            // t*2 + dup
__device__ float  g_part[(size_t)2 * T_TOK * H_DIM];  // per-dup partials
// Pre-swizzled A stage tiles (8KB = 4096 halves each):
__device__ __half g_xs  [(size_t)E_NUM * 32 * 64 * 4096];
__device__ __half g_acts[(size_t)E_NUM * 32 * 24 * 4096];
// Pre-swizzled B stage tiles (16KB = 8192 halves each):
__device__ __half g_w01s[(size_t)E_NUM * 6 * 64 * 8192];
__device__ __half g_wos [(size_t)E_NUM * 8 * 24 * 8192];

// ============================ helpers ====================================
__device__ __forceinline__ uint32_t smem_u32(const void* p) {
    uint32_t a;
    asm("{ .reg .u64 t; cvta.to.shared.u64 t, %1; cvt.u32.u64 %0, t; }" : "=r"(a) : "l"(p));
    return a;
}
__device__ __forceinline__ void ldm_x4(uint32_t* r, uint32_t a) {
    asm volatile("ldmatrix.sync.aligned.m8n8.x4.shared.b16 {%0,%1,%2,%3}, [%4];"
                 : "=r"(r[0]), "=r"(r[1]), "=r"(r[2]), "=r"(r[3]) : "r"(a));
}
__device__ __forceinline__ void ldm_x4_t(uint32_t* r, uint32_t a) {
    asm volatile("ldmatrix.sync.aligned.m8n8.x4.trans.shared.b16 {%0,%1,%2,%3}, [%4];"
                 : "=r"(r[0]), "=r"(r[1]), "=r"(r[2]), "=r"(r[3]) : "r"(a));
}
__device__ __forceinline__ void mma16816(float* c, const uint32_t* a, uint32_t b0, uint32_t b1) {
    asm volatile("mma.sync.aligned.m16n8k16.row.col.f32.f16.f16.f32 "
                 "{%0,%1,%2,%3}, {%4,%5,%6,%7}, {%8,%9}, {%0,%1,%2,%3};"
                 : "+f"(c[0]), "+f"(c[1]), "+f"(c[2]), "+f"(c[3])
                 : "r"(a[0]), "r"(a[1]), "r"(a[2]), "r"(a[3]), "r"(b0), "r"(b1));
}
__device__ __forceinline__ void bulkN(uint32_t dst, const void* src, uint32_t bytes,
                                      uint32_t mbar) {
    asm volatile("cp.async.bulk.shared::cta.global.mbarrier::complete_tx::bytes "
                 "[%0], [%1], %2, [%3];"
                 :: "r"(dst), "l"(src), "r"(bytes), "r"(mbar) : "memory");
}
#define FENCE_PROXY_ASYNC() asm volatile("fence.proxy.async.shared::cta;" ::: "memory")
#define MBAR_INIT(a, c) \
    asm volatile("mbarrier.init.shared.b64 [%0], %1;" :: "r"(a), "r"((uint32_t)(c)) : "memory")
#define MBAR_EXPECT(a, b) \
    asm volatile("mbarrier.arrive.expect_tx.shared.b64 _, [%0], %1;" :: "r"(a), "r"((uint32_t)(b)) : "memory")
#define MBAR_WAIT(a, p) do {                                                  \
    uint32_t _m = (a), _p = (p), _d;                                          \
    asm volatile("{\n\t.reg .pred q;\n\t"                                     \
        "mbarrier.try_wait.parity.shared.b64 q, [%1], %2;\n\t"                \
        "selp.b32 %0, 1, 0, q;\n\t}" : "=r"(_d) : "r"(_m), "r"(_p) : "memory"); \
    while (!_d) {                                                             \
        asm volatile("{\n\t.reg .pred q;\n\t"                                 \
            "mbarrier.try_wait.parity.shared.b64 q, [%1], %2;\n\t"            \
            "selp.b32 %0, 1, 0, q;\n\t}" : "=r"(_d) : "r"(_m), "r"(_p) : "memory"); \
    }                                                                         \
} while (0)

// convert 8 fp32 -> 8 fp16 (packed uint4)
__device__ __forceinline__ void cvt8(float4 a, float4 b, uint4& H) {
    __half2 h0 = __floats2half2_rn(a.x, a.y);
    __half2 h1 = __floats2half2_rn(a.z, a.w);
    __half2 h2 = __floats2half2_rn(b.x, b.y);
    __half2 h3 = __floats2half2_rn(b.z, b.w);
    H.x = *(uint32_t*)&h0; H.y = *(uint32_t*)&h1;
    H.z = *(uint32_t*)&h2; H.w = *(uint32_t*)&h3;
}

// ---------------------------------------------------------------------------
__global__ void k_init() { if (threadIdx.x < E_NUM) g_cnt[threadIdx.x] = 0; }

// ---------------------------------------------------------------------------
__global__ void k_router(const float* __restrict__ x, const float* __restrict__ wr,
                         float* __restrict__ out_logits, int write_logits) {
    int warp = threadIdx.x >> 5, lane = threadIdx.x & 31;
    int t = blockIdx.x * 8 + warp;
    if (t >= T_TOK) return;
    float acc[E_NUM];
#pragma unroll
    for (int e = 0; e < E_NUM; e++) acc[e] = 0.f;
    const float* xp = x + (size_t)t * H_DIM;
    for (int h = lane; h < H_DIM; h += 32) {
        float xv = xp[h];
        const float* w = wr + (size_t)h * E_NUM;
#pragma unroll
        for (int e = 0; e < E_NUM; e++) acc[e] += xv * w[e];
    }
#pragma unroll
    for (int e = 0; e < E_NUM; e++)
#pragma unroll
        for (int o = 16; o > 0; o >>= 1)
            acc[e] += __shfl_xor_sync(0xffffffffu, acc[e], o);
    if (lane == 0) {
        if (write_logits)
#pragma unroll
            for (int e = 0; e < E_NUM; e++)
                out_logits[(size_t)t * E_NUM + e] = acc[e];
        int i1 = 0;
#pragma unroll
        for (int e = 1; e < E_NUM; e++) if (acc[e] > acc[i1]) i1 = e;
        int i2 = (i1 == 0) ? 1 : 0;
#pragma unroll
        for (int e = 0; e < E_NUM; e++)
            if (e != i1 && acc[e] > acc[i2]) i2 = e;
        float p2 = expf(acc[i2] - acc[i1]);
        float w1 = 1.f / (1.f + p2), w2 = p2 * w1;
        int p;
        p = atomicAdd(&g_cnt[i1], 1);
        g_tok[i1 * T_TOK + p] = t; g_wt[i1 * T_TOK + p] = w1;
        g_dst[i1 * T_TOK + p] = t * 2;
        p = atomicAdd(&g_cnt[i2], 1);
        g_tok[i2 * T_TOK + p] = t; g_wt[i2 * T_TOK + p] = w2;
        g_dst[i2 * T_TOK + p] = t * 2 + 1;
    }
}

// ---------------------------------------------------------------------------
// Pre-swizzle mlp1 B tiles: one thread per 16B unit.
__global__ void k_swz1(const float* __restrict__ wi0, const float* __restrict__ wi1) {
    const int TOT = E_NUM * 6 * 65536;
    int i = blockIdx.x * blockDim.x + threadIdx.x;
    if (i >= TOT) return;
    int nat = i & 31;
    int kk  = (i >> 5) & 15;
    int sub = (i >> 9) & 1;
    int kc  = (i >> 10) & 63;
    int r   = i >> 16;                 // e*6 + i0t
    int i0t = r % 6, e = r / 6;
    int k  = kc * 32 + sub * 16 + kk;
    int ic = i0t * 128 + (nat >> 1) * 8;
    const float* src = ((nat & 1) ? wi1 : wi0) +
                       ((size_t)e * H_DIM + k) * I_DIM + ic;
    float4 a = *(const float4*)src, b = *(const float4*)(src + 4);
    uint4 H_; cvt8(a, b, H_);
    size_t dst = ((size_t)r * 64 + kc) * 8192 + sub * 4096 + kk * 256 +
                 ((uint32_t)(nat ^ (kk & 7)) << 3);
    *(uint4*)(g_w01s + dst) = H_;
}

// Pre-swizzle mlp2 B tiles.
__global__ void k_swz2(const float* __restrict__ wo) {
    const int TOT = E_NUM * 8 * 24 * 1024;
    int i = blockIdx.x * blockDim.x + threadIdx.x;
    if (i >= TOT) return;
    int nat = i & 31;
    int kk  = (i >> 5) & 15;
    int sub = (i >> 9) & 1;
    int t   = i >> 10;
    int kc  = t % 24;
    int r   = t / 24;                  // e*8 + n0t
    int n0t = r % 8, e = r / 8;
    int k = kc * 32 + sub * 16 + kk;
    int h = n0t * 256 + nat * 8;
    const float* src = wo + ((size_t)e * I_DIM + k) * H_DIM + h;
    float4 a = *(const float4*)src, b = *(const float4*)(src + 4);
    uint4 H_; cvt8(a, b, H_);
    size_t dst = ((size_t)r * 24 + kc) * 8192 + sub * 4096 + kk * 256 +
                 ((uint32_t)(nat ^ (kk & 7)) << 3);
    *(uint4*)(g_wos + dst) = H_;
}

// Gather routed token rows into pre-swizzled A tiles (after router).
__global__ void k_gath(const float* __restrict__ x) {
    int i = blockIdx.x * blockDim.x + threadIdx.x;
    if (i >= E_NUM * 32 * 64 * 512) return;
    int u    = i & 1;
    int row  = (i >> 1) & 127;
    int sub  = (i >> 8) & 1;
    int kc   = (i >> 9) & 63;
    int m0t  = (i >> 15) & 31;
    int e    = i >> 20;
    int ne = g_cnt[e];
    if (m0t * 128 >= ne) return;
    int slot = m0t * 128 + row;
    uint4 H_ = make_uint4(0, 0, 0, 0);
    if (slot < ne) {
        int tok = g_tok[e * T_TOK + slot];
        int k = kc * 32 + sub * 16 + u * 8;
        const float* s = x + (size_t)tok * H_DIM + k;
        cvt8(*(const float4*)s, *(const float4*)(s + 4), H_);
    }
    size_t dst = (((size_t)(e * 32 + m0t) * 64 + kc) * 4096) + sub * 2048 +
                 row * 16 + (uint32_t)((u * 8) ^ (((row >> 2) & 1) << 3));
    *(uint4*)(g_xs + dst) = H_;
}

// Combine: out[t][h] = part[2t][h] + part[2t+1][h]
__global__ void k_comb(float* __restrict__ out) {
    int i = blockIdx.x * blockDim.x + threadIdx.x;
    const int N4 = T_TOK * H_DIM / 4;
    if (i >= N4) return;
    int t  = i / (H_DIM / 4);
    int h4 = i % (H_DIM / 4);
    const float4* p0 = (const float4*)(g_part + ((size_t)2 * t)     * H_DIM) + h4;
    const float4* p1 = (const float4*)(g_part + ((size_t)2 * t + 1) * H_DIM) + h4;
    float4 a = *p0, b = *p1;
    float4 r = make_float4(a.x + b.x, a.y + b.y, a.z + b.z, a.w + b.w);
    ((float4*)(out + (size_t)t * H_DIM))[h4] = r;
}

// ---------------------------------------------------------------------------
// GEMM geometry: BM=128, BN=256, BK=32, 256 thr, warps 2(M)x4(N), warp 64x64.
// Stage (24576B) = [A 8K | B 16K], BOTH filled by cp.async.bulk from
// pre-swizzled gmem tiles; one mbarrier per stage. 3 stages.
#define STAGE_B 24576
#define NSTAGE  3
#define SMEM_TOTAL (NSTAGE * STAGE_B + 64)

#define COMPUTE_SUB(AB, BB)                                                   \
    do {                                                                      \
        uint32_t Af[4][4];                                                    \
        _Pragma("unroll")                                                     \
        for (int i = 0; i < 4; i++) {                                         \
            int row = arow_l + i * 16;                                        \
            uint32_t ad = (AB) + row * 32 +                                   \
                          (acol_l ^ ((((uint32_t)row >> 2) & 1) << 4));       \
            ldm_x4(Af[i], ad);                                                \
        }                                                                     \
        _Pragma("unroll")                                                     \
        for (int jj = 0; jj < 4; jj++) {                                      \
            uint32_t Bf[4];                                                   \
            uint32_t nat = (uint32_t)(bnat_l + jj * 2);                       \
            uint32_t bd = (BB) + bk_l * 512 +                                 \
                          ((nat ^ ((uint32_t)bk_l & 7)) << 4);                \
            ldm_x4_t(Bf, bd);                                                 \
            _Pragma("unroll")                                                 \
            for (int i = 0; i < 4; i++) {                                     \
                mma16816(c[i][jj * 2],     Af[i], Bf[0], Bf[1]);              \
                mma16816(c[i][jj * 2 + 1], Af[i], Bf[2], Bf[3]);              \
            }                                                                 \
        }                                                                     \
    } while (0)

#define ISSUE_BULK(S, C) do {                                                 \
    if (tid == 0) {                                                           \
        uint32_t s_ = sbase + (S) * STAGE_B;                                  \
        FENCE_PROXY_ASYNC();                                                  \
        MBAR_EXPECT(mb + (S) * 8, 24576);                                     \
        bulkN(s_,        asrc + (size_t)(C) * 4096, 8192,  mb + (S) * 8);     \
        bulkN(s_ + 8192, bsrc + (size_t)(C) * 8192, 16384, mb + (S) * 8);     \
    }                                                                         \
} while (0)

// GEMM1: per expert, [Ne,H] x [H, 128 gate + 128 up interleaved by 8] -> act
__global__ __launch_bounds__(256, 1)
void k_mlp1() {
    extern __shared__ __align__(16) char sm[];
    int e   = blockIdx.z;
    int ne  = g_cnt[e];
    int m0t = blockIdx.x;
    int m0  = m0t * 128;
    if (m0 >= ne) return;
    int i0t = blockIdx.y;
    int i0  = i0t * 128;

    int tid = threadIdx.x, lane = tid & 31, wid = tid >> 5;
    int warpM = (wid >> 2) * 64, warpN = (wid & 3) * 64;
    uint32_t sbase = smem_u32(sm);
    uint32_t mb = sbase + NSTAGE * STAGE_B;

    if (tid == 0) {
#pragma unroll
        for (int s = 0; s < NSTAGE; s++) MBAR_INIT(mb + s * 8, 1);
    }
    __syncthreads();

    const __half* asrc = g_xs   + ((size_t)(e * 32 + m0t) * 64) * 4096;
    const __half* bsrc = g_w01s + ((size_t)(e * 6 + i0t) * 64) * 8192;

    float c[4][8][4];
#pragma unroll
    for (int i = 0; i < 4; i++)
#pragma unroll
        for (int j = 0; j < 8; j++)
#pragma unroll
            for (int q = 0; q < 4; q++) c[i][j][q] = 0.f;

    ISSUE_BULK(0, 0); ISSUE_BULK(1, 1);

    int arow_l = warpM + (lane & 15);
    uint32_t acol_l = (uint32_t)((lane >> 4) * 16);
    int bk_l = (lane & 7) + ((lane >> 3) & 1) * 8;
    int bnat_l = (warpN >> 3) + ((lane >> 4) & 1);

    const int NC = H_DIM / 32;  // 64
    for (int cc = 0; cc < NC; cc++) {
        MBAR_WAIT(mb + (cc % 3) * 8, (cc / 3) & 1);
        __syncthreads();
        if (cc + 2 < NC) ISSUE_BULK((cc + 2) % 3, cc + 2);
        uint32_t st = sbase + (cc % 3) * STAGE_B;
        COMPUTE_SUB(st,        st + 8192);
        COMPUTE_SUB(st + 4096, st + 16384);
    }

    // Epilogue: pairs (2jj, 2jj+1) = (gate, up); silu -> pre-swizzled act tile
    int gr = lane >> 2, gc = (lane & 3) * 2;
#pragma unroll
    for (int i = 0; i < 4; i++) {
#pragma unroll
        for (int jj = 0; jj < 4; jj++) {
            int jg = jj * 2, ju = jj * 2 + 1;
            int icg = i0 + ((wid & 3) * 4 + jj) * 8 + gc;
#pragma unroll
            for (int hf = 0; hf < 2; hf++) {
                int r = warpM + i * 16 + gr + hf * 8;
                if (m0 + r < ne) {
                    float g0 = c[i][jg][2 * hf], g1 = c[i][jg][2 * hf + 1];
                    float u0 = c[i][ju][2 * hf], u1 = c[i][ju][2 * hf + 1];
                    float a0 = (g0 / (1.f + expf(-g0))) * u0;
                    float a1 = (g1 / (1.f + expf(-g1))) * u1;
                    __half2 hh = __floats2half2_rn(a0, a1);
                    int kc2 = icg >> 5, sub2 = (icg >> 4) & 1;
                    int u2 = (icg >> 3) & 1, b2 = icg & 7;
                    size_t off = (((size_t)(e * 32 + m0t) * 24 + kc2) * 4096) +
                                 sub2 * 2048 + r * 16 +
                                 (uint32_t)((u2 * 8) ^ (((r >> 2) & 1) << 3)) + b2;
                    *(uint32_t*)(g_acts + off) = *(uint32_t*)&hh;
                }
            }
        }
    }
}

// ---------------------------------------------------------------------------
__global__ __launch_bounds__(256, 1)
void k_mlp2() {
    extern __shared__ __align__(16) char sm[];
    int e   = blockIdx.z;
    int ne  = g_cnt[e];
    int m0t = blockIdx.x;
    int m0  = m0t * 128;
    if (m0 >= ne) return;
    int n0t = blockIdx.y;
    int n0  = n0t * 256;

    int tid = threadIdx.x, lane = tid & 31, wid = tid >> 5;
    int warpM = (wid >> 2) * 64, warpN = (wid & 3) * 64;
    uint32_t sbase = smem_u32(sm);
    uint32_t mb = sbase + NSTAGE * STAGE_B;

    if (tid == 0) {
#pragma unroll
        for (int s = 0; s < NSTAGE; s++) MBAR_INIT(mb + s * 8, 1);
    }
    __syncthreads();

    const __half* asrc = g_acts + ((size_t)(e * 32 + m0t) * 24) * 4096;
    const __half* bsrc = g_wos  + ((size_t)(e * 8 + n0t) * 24) * 8192;

    float c[4][8][4];
#pragma unroll
    for (int i = 0; i < 4; i++)
#pragma unroll
        for (int j = 0; j < 8; j++)
#pragma unroll
            for (int q = 0; q < 4; q++) c[i][j][q] = 0.f;

    ISSUE_BULK(0, 0); ISSUE_BULK(1, 1);

    int arow_l = warpM + (lane & 15);
    uint32_t acol_l = (uint32_t)((lane >> 4) * 16);
    int bk_l = (lane & 7) + ((lane >> 3) & 1) * 8;
    int bnat_l = (warpN >> 3) + ((lane >> 4) & 1);

    const int NC = I_DIM / 32;  // 24
    for (int cc = 0; cc < NC; cc++) {
        MBAR_WAIT(mb + (cc % 3) * 8, (cc / 3) & 1);
        __syncthreads();
        if (cc + 2 < NC) ISSUE_BULK((cc + 2) % 3, cc + 2);
        uint32_t st = sbase + (cc % 3) * STAGE_B;
        COMPUTE_SUB(st,        st + 8192);
        COMPUTE_SUB(st + 4096, st + 16384);
    }

    // Epilogue: weighted STG.64 into per-dup partial buffer (no atomics).
    int gr = lane >> 2, gc = (lane & 3) * 2;
#pragma unroll
    for (int i = 0; i < 4; i++) {
#pragma unroll
        for (int hf = 0; hf < 2; hf++) {
            int r = m0 + warpM + i * 16 + gr + hf * 8;
            if (r < ne) {
                int   d = g_dst[e * T_TOK + r];
                float w = g_wt [e * T_TOK + r];
                float* op = g_part + (size_t)d * H_DIM + n0 + warpN;
#pragma unroll
                for (int j = 0; j < 8; j++) {
                    float2 v = make_float2(w * c[i][j][2 * hf],
                                           w * c[i][j][2 * hf + 1]);
                    *(float2*)(op + j * 8 + gc) = v;
                }
            }
        }
    }
}

// ---------------------------------------------------------------------------
extern "C" void kernel_launch(void* const* d_in, const int* in_sizes, int n_in,
                              void* d_out, int out_size) {
    const float* x   = (const float*)d_in[0];
    const float* wr  = (const float*)d_in[1];
    const float* wi0 = (const float*)d_in[2];
    const float* wi1 = (const float*)d_in[3];
    const float* wo  = (const float*)d_in[4];
    float* out = (float*)d_out;

    cudaFuncSetAttribute(k_mlp1, cudaFuncAttributeMaxDynamicSharedMemorySize, SMEM_TOTAL);
    cudaFuncSetAttribute(k_mlp2, cudaFuncAttributeMaxDynamicSharedMemorySize, SMEM_TOTAL);

    int write_logits = (out_size >= T_TOK * H_DIM + T_TOK * E_NUM) ? 1 : 0;

    k_init<<<1, 32>>>();
    k_router<<<T_TOK / 8, 256>>>(x, wr, out + (size_t)T_TOK * H_DIM, write_logits);

    k_swz1<<<(E_NUM * 6 * 65536 + 255) / 256, 256>>>(wi0, wi1);
    k_swz2<<<(E_NUM * 8 * 24 * 1024 + 255) / 256, 256>>>(wo);
    k_gath<<<(E_NUM * 32 * 64 * 512 + 255) / 256, 256>>>(x);

    dim3 g1(32, 6, E_NUM);
    k_mlp1<<<g1, 256, SMEM_TOTAL>>>();

    dim3 g2(32, 8, E_NUM);
    k_mlp2<<<g2, 256, SMEM_TOTAL>>>();

    k_comb<<<(T_TOK * H_DIM / 4 + 255) / 256, 256>>>(out);
}